// round 5
// baseline (speedup 1.0000x reference)
#include <cuda_runtime.h>
#include <cuda_bf16.h>
#include <cstdint>

#define HW   4096
#define CIN  256
#define CMID 128
#define NB   4

// ---------------- scratch ----------------
__device__ __nv_bfloat16 g_qT[NB*HW*CMID];   // [n][t][c]  (pre-scaled by log2e/64)
__device__ __nv_bfloat16 g_kT[NB*HW*CMID];   // [n][s][c]
__device__ __nv_bfloat16 g_vT[NB*HW*CMID];   // [n][s][c]
__device__ __nv_bfloat16 g_zT[NB*HW*CMID];   // [n][t][c]

// rotation multipliers 2^r for r = {13,15,26,6,17,29,16,24}; kept in __constant__
// so ptxas cannot strength-reduce IMAD.WIDE back into SHF (pipe balance!)
__constant__ uint32_t c_rm[8] = {
    1u<<13, 1u<<15, 1u<<26, 1u<<6, 1u<<17, 1u<<29, 1u<<16, 1u<<24
};

// q pre-scale: log2(e)/64  (softmax exp becomes bare ex2)
#define QSCALE 0.0225421100f

// ---------------- threefry2x32 (JAX partitionable), pipe-balanced ----------------
// round: x0 += x1; x1 = rotl(x1,r) ^ x0
//   rotl+xor = IMAD.WIDE.U32 (fma pipe) + LOP3 (lo|hi)^x0 (alu pipe)
__device__ __forceinline__ void thf_round(uint32_t& x0, uint32_t& x1, uint32_t mul) {
    x0 += x1;
    uint64_t p = (uint64_t)x1 * (uint64_t)mul;
    uint32_t lo = (uint32_t)p, hi = (uint32_t)(p >> 32);
    asm("lop3.b32 %0, %1, %2, %3, 0x56;\n" : "=r"(x1) : "r"(lo), "r"(hi), "r"(x0));
}
__device__ __forceinline__ uint32_t thf_bits(uint32_t f, const uint32_t* rm) {
    const uint32_t K1 = 42u;
    const uint32_t K2 = 0x1BD11BDAu ^ 42u;
    uint32_t x0 = 0u, x1 = f + K1;
    thf_round(x0,x1,rm[0]); thf_round(x0,x1,rm[1]); thf_round(x0,x1,rm[2]); thf_round(x0,x1,rm[3]);
    x0 += K1; x1 += K2 + 1u;
    thf_round(x0,x1,rm[4]); thf_round(x0,x1,rm[5]); thf_round(x0,x1,rm[6]); thf_round(x0,x1,rm[7]);
    x0 += K2; x1 += 2u;
    thf_round(x0,x1,rm[0]); thf_round(x0,x1,rm[1]); thf_round(x0,x1,rm[2]); thf_round(x0,x1,rm[3]);
    x1 += K1 + 3u;                      // x0 += K0 (=0)
    thf_round(x0,x1,rm[4]); thf_round(x0,x1,rm[5]); thf_round(x0,x1,rm[6]); thf_round(x0,x1,rm[7]);
    x0 += K1; x1 += K2 + 4u;
    thf_round(x0,x1,rm[0]); thf_round(x0,x1,rm[1]); thf_round(x0,x1,rm[2]); thf_round(x0,x1,rm[3]);
    x0 += K2; x1 += 5u;
    return x0 ^ x1;
}
// mask <=> (bits>>9) < 838861  <=>  bits < 838861*512
#define MASK_THRESH 429496832u

__device__ __forceinline__ float ex2f_(float x) {
    float r;
    asm("ex2.approx.f32 %0, %1;\n" : "=f"(r) : "f"(x));
    return r;
}

// ---------------- mma helpers ----------------
__device__ __forceinline__ void cp16(void* dst, const void* src) {
    uint32_t d = (uint32_t)__cvta_generic_to_shared(dst);
    asm volatile("cp.async.cg.shared.global [%0], [%1], 16;\n" :: "r"(d), "l"(src));
}
__device__ __forceinline__ void ldsm_x4(uint32_t& a0, uint32_t& a1, uint32_t& a2, uint32_t& a3, const void* p) {
    uint32_t s = (uint32_t)__cvta_generic_to_shared(p);
    asm volatile("ldmatrix.sync.aligned.m8n8.x4.shared.b16 {%0,%1,%2,%3}, [%4];\n"
                 : "=r"(a0), "=r"(a1), "=r"(a2), "=r"(a3) : "r"(s));
}
__device__ __forceinline__ void ldsm_x2(uint32_t& b0, uint32_t& b1, const void* p) {
    uint32_t s = (uint32_t)__cvta_generic_to_shared(p);
    asm volatile("ldmatrix.sync.aligned.m8n8.x2.shared.b16 {%0,%1}, [%2];\n"
                 : "=r"(b0), "=r"(b1) : "r"(s));
}
__device__ __forceinline__ void ldsm_x2t(uint32_t& b0, uint32_t& b1, const void* p) {
    uint32_t s = (uint32_t)__cvta_generic_to_shared(p);
    asm volatile("ldmatrix.sync.aligned.m8n8.x2.trans.shared.b16 {%0,%1}, [%2];\n"
                 : "=r"(b0), "=r"(b1) : "r"(s));
}
__device__ __forceinline__ void mma16816(float* d, uint32_t a0, uint32_t a1, uint32_t a2, uint32_t a3,
                                         uint32_t b0, uint32_t b1) {
    asm volatile("mma.sync.aligned.m16n8k16.row.col.f32.bf16.bf16.f32 "
                 "{%0,%1,%2,%3}, {%4,%5,%6,%7}, {%8,%9}, {%0,%1,%2,%3};\n"
                 : "+f"(d[0]), "+f"(d[1]), "+f"(d[2]), "+f"(d[3])
                 : "r"(a0), "r"(a1), "r"(a2), "r"(a3), "r"(b0), "r"(b1));
}
__device__ __forceinline__ uint32_t pack_bf2(float lo, float hi) {
    __nv_bfloat162 h = __floats2bfloat162_rn(lo, hi);
    return *(uint32_t*)&h;
}

// ---------------- kernel 1: q/k/v projection (tensor core) ----------------
#define QKV_SMEM 135168
__global__ void __launch_bounds__(256, 1)
k_qkv(const float* __restrict__ x,
      const float* __restrict__ wq, const float* __restrict__ bq,
      const float* __restrict__ wk, const float* __restrict__ bk,
      const float* __restrict__ wv, const float* __restrict__ bv)
{
    extern __shared__ char sm8[];
    __nv_bfloat16* Xs = (__nv_bfloat16*)sm8;              // [128 t][264 c]
    __nv_bfloat16* Ws = (__nv_bfloat16*)(sm8 + 67584);    // [128 o][264 c] / stage [128][136]

    const int tid = threadIdx.x, lane = tid & 31, wid = tid >> 5;
    const int t0 = blockIdx.x * 128, n = blockIdx.y;
    const int g = lane >> 2, tg = lane & 3;

    for (int i = tid; i < 256*32; i += 256) {
        int c = i >> 5, t4 = (i & 31) * 4;
        float4 v = *(const float4*)(x + (size_t)(n*CIN + c)*HW + t0 + t4);
        Xs[(t4+0)*264 + c] = __float2bfloat16(v.x);
        Xs[(t4+1)*264 + c] = __float2bfloat16(v.y);
        Xs[(t4+2)*264 + c] = __float2bfloat16(v.z);
        Xs[(t4+3)*264 + c] = __float2bfloat16(v.w);
    }

#pragma unroll 1
    for (int m = 0; m < 3; m++) {
        const float* wp = (m == 0) ? wq : (m == 1) ? wk : wv;
        const float* bp = (m == 0) ? bq : (m == 1) ? bk : bv;
        const float sc = (m == 0) ? QSCALE : 1.0f;
        __syncthreads();
        for (int i = tid; i < 128*64; i += 256) {
            int o = i >> 6, c4 = (i & 63) * 4;
            float4 v = *(const float4*)(wp + o*CIN + c4);
            Ws[o*264 + c4 + 0] = __float2bfloat16(v.x);
            Ws[o*264 + c4 + 1] = __float2bfloat16(v.y);
            Ws[o*264 + c4 + 2] = __float2bfloat16(v.z);
            Ws[o*264 + c4 + 3] = __float2bfloat16(v.w);
        }
        __syncthreads();

        float acc[16][4];
#pragma unroll
        for (int j = 0; j < 16; j++)
#pragma unroll
            for (int q = 0; q < 4; q++) acc[j][q] = 0.f;

#pragma unroll
        for (int kk = 0; kk < 16; kk++) {
            uint32_t a0, a1, a2, a3;
            ldsm_x4(a0, a1, a2, a3, Xs + (wid*16 + (lane & 15))*264 + kk*16 + (lane >> 4)*8);
#pragma unroll
            for (int j = 0; j < 16; j++) {
                uint32_t b0, b1;
                ldsm_x2(b0, b1, Ws + (j*8 + (lane & 7))*264 + kk*16 + ((lane >> 3) & 1)*8);
                mma16816(acc[j], a0, a1, a2, a3, b0, b1);
            }
        }
        __syncthreads();

        __nv_bfloat16* Tb = Ws;   // [128][136]
#pragma unroll
        for (int j = 0; j < 16; j++) {
            int o = j*8 + tg*2;
            float b0 = __ldg(bp + o), b1 = __ldg(bp + o + 1);
            Tb[(wid*16 + g)*136 + o]         = __float2bfloat16((acc[j][0] + b0) * sc);
            Tb[(wid*16 + g)*136 + o + 1]     = __float2bfloat16((acc[j][1] + b1) * sc);
            Tb[(wid*16 + g + 8)*136 + o]     = __float2bfloat16((acc[j][2] + b0) * sc);
            Tb[(wid*16 + g + 8)*136 + o + 1] = __float2bfloat16((acc[j][3] + b1) * sc);
        }
        __syncthreads();
        __nv_bfloat16* gdst = (m == 0) ? g_qT : (m == 1) ? g_kT : g_vT;
        for (int i = tid; i < 128*16; i += 256) {
            int r = i >> 4, ch = i & 15;
            *(uint4*)(gdst + (size_t)(n*HW + t0 + r)*CMID + ch*8) =
                *(const uint4*)(Tb + r*136 + ch*8);
        }
    }
}

// ---------------- kernel 2: tensor-core attention, s-tile 128 ----------------
#define ATTN_SMEM 174080
__global__ void __launch_bounds__(256, 1)
k_attn()
{
    extern __shared__ char sm8[];
    __nv_bfloat16* Qs  = (__nv_bfloat16*)sm8;               // [128][136]
    __nv_bfloat16* Kb0 = (__nv_bfloat16*)(sm8 + 34816);
    __nv_bfloat16* Kb1 = (__nv_bfloat16*)(sm8 + 69632);
    __nv_bfloat16* Vb0 = (__nv_bfloat16*)(sm8 + 104448);
    __nv_bfloat16* Vb1 = (__nv_bfloat16*)(sm8 + 139264);

    const int tid = threadIdx.x, lane = tid & 31, wid = tid >> 5;
    const int t0 = blockIdx.x * 128, n = blockIdx.y;
    const int g = lane >> 2, tg = lane & 3;

    uint32_t rm[8];
#pragma unroll
    for (int i = 0; i < 8; i++) rm[i] = c_rm[i];

    for (int i = tid; i < 128*16; i += 256) {
        int r = i >> 4, ch = i & 15;
        size_t go = (size_t)(n*HW + r)*CMID + ch*8;
        cp16(Qs  + r*136 + ch*8, g_qT + (size_t)(n*HW + t0 + r)*CMID + ch*8);
        cp16(Kb0 + r*136 + ch*8, g_kT + go);
        cp16(Vb0 + r*136 + ch*8, g_vT + go);
    }
    asm volatile("cp.async.commit_group;\n");

    float Z[16][4];
#pragma unroll
    for (int jc = 0; jc < 16; jc++)
#pragma unroll
        for (int q = 0; q < 4; q++) Z[jc][q] = 0.f;
    float dsum0 = 0.f, dsum1 = 0.f;

#pragma unroll 1
    for (int it = 0; it < 32; it++) {
        const __nv_bfloat16* K_ = (it & 1) ? Kb1 : Kb0;
        const __nv_bfloat16* V_ = (it & 1) ? Vb1 : Vb0;
        if (it + 1 < 32) {
            __nv_bfloat16* Kn = ((it+1) & 1) ? Kb1 : Kb0;
            __nv_bfloat16* Vn = ((it+1) & 1) ? Vb1 : Vb0;
            int s0n = (it + 1) * 128;
            for (int i = tid; i < 128*16; i += 256) {
                int r = i >> 4, ch = i & 15;
                size_t go = (size_t)(n*HW + s0n + r)*CMID + ch*8;
                cp16(Kn + r*136 + ch*8, g_kT + go);
                cp16(Vn + r*136 + ch*8, g_vT + go);
            }
            asm volatile("cp.async.commit_group;\n");
            asm volatile("cp.async.wait_group 1;\n");
        } else {
            asm volatile("cp.async.wait_group 0;\n");
        }
        __syncthreads();

        // ---- GEMM1: S[16t x 128s] ----
        float S[16][4];
#pragma unroll
        for (int j = 0; j < 16; j++)
#pragma unroll
            for (int q = 0; q < 4; q++) S[j][q] = 0.f;
#pragma unroll
        for (int kk = 0; kk < 8; kk++) {
            uint32_t a0, a1, a2, a3;
            ldsm_x4(a0, a1, a2, a3, Qs + (wid*16 + (lane & 15))*136 + kk*16 + (lane >> 4)*8);
#pragma unroll
            for (int j = 0; j < 16; j++) {
                uint32_t b0, b1;
                ldsm_x2(b0, b1, K_ + (j*8 + (lane & 7))*136 + kk*16 + ((lane >> 3) & 1)*8);
                mma16816(S[j], a0, a1, a2, a3, b0, b1);
            }
        }

        // ---- mask (balanced threefry) + ex2 ----
        const int s0 = it * 128;
        const uint32_t fb0 = ((uint32_t)n << 24) + (uint32_t)(t0 + wid*16 + g)*4096u
                           + (uint32_t)(s0 + tg*2);
        const uint32_t fb1 = fb0 + 8u*4096u;
#pragma unroll
        for (int j = 0; j < 16; j++) {
            uint32_t f0 = fb0 + (uint32_t)(j*8);
            uint32_t f1 = fb1 + (uint32_t)(j*8);
            S[j][0] = (thf_bits(f0,    rm) < MASK_THRESH) ? 0.f : ex2f_(S[j][0]);
            S[j][1] = (thf_bits(f0+1u, rm) < MASK_THRESH) ? 0.f : ex2f_(S[j][1]);
            S[j][2] = (thf_bits(f1,    rm) < MASK_THRESH) ? 0.f : ex2f_(S[j][2]);
            S[j][3] = (thf_bits(f1+1u, rm) < MASK_THRESH) ? 0.f : ex2f_(S[j][3]);
            dsum0 += S[j][0] + S[j][1];
            dsum1 += S[j][2] + S[j][3];
        }

        // ---- GEMM2: Z[16t x 128c] += P * V ----
#pragma unroll
        for (int m = 0; m < 8; m++) {
            uint32_t pa0 = pack_bf2(S[2*m][0],   S[2*m][1]);
            uint32_t pa1 = pack_bf2(S[2*m][2],   S[2*m][3]);
            uint32_t pa2 = pack_bf2(S[2*m+1][0], S[2*m+1][1]);
            uint32_t pa3 = pack_bf2(S[2*m+1][2], S[2*m+1][3]);
#pragma unroll
            for (int jc = 0; jc < 16; jc++) {
                uint32_t b0, b1;
                ldsm_x2t(b0, b1, V_ + (m*16 + (lane & 7) + ((lane >> 3) & 1)*8)*136 + jc*8);
                mma16816(Z[jc], pa0, pa1, pa2, pa3, b0, b1);
            }
        }
        __syncthreads();
    }

    // ---- row denominators (quad reduce) ----
    dsum0 += __shfl_xor_sync(0xffffffffu, dsum0, 1);
    dsum0 += __shfl_xor_sync(0xffffffffu, dsum0, 2);
    dsum1 += __shfl_xor_sync(0xffffffffu, dsum1, 1);
    dsum1 += __shfl_xor_sync(0xffffffffu, dsum1, 2);
    const float inv0 = 1.f / dsum0, inv1 = 1.f / dsum1;

    // ---- stage zT[t][c] bf16, coalesced store ----
    __nv_bfloat16* Tb = Kb0;   // [128][136]
#pragma unroll
    for (int jc = 0; jc < 16; jc++) {
        int c = jc*8 + tg*2;
        Tb[(wid*16 + g)*136 + c]         = __float2bfloat16(Z[jc][0] * inv0);
        Tb[(wid*16 + g)*136 + c + 1]     = __float2bfloat16(Z[jc][1] * inv0);
        Tb[(wid*16 + g + 8)*136 + c]     = __float2bfloat16(Z[jc][2] * inv1);
        Tb[(wid*16 + g + 8)*136 + c + 1] = __float2bfloat16(Z[jc][3] * inv1);
    }
    __syncthreads();
    for (int i = tid; i < 128*16; i += 256) {
        int r = i >> 4, ch = i & 15;
        *(uint4*)(g_zT + (size_t)(n*HW + t0 + r)*CMID + ch*8) =
            *(const uint4*)(Tb + r*136 + ch*8);
    }
}

// ---------------- kernel 3: output projection + residual (tensor core) ----------------
#define OUT_SMEM 69632
__global__ void __launch_bounds__(256, 1)
k_out(const float* __restrict__ x, const float* __restrict__ wz,
      const float* __restrict__ bz, float* __restrict__ out)
{
    extern __shared__ char sm8[];
    __nv_bfloat16* Wzs = (__nv_bfloat16*)sm8;               // [128 o][136 c]
    __nv_bfloat16* Zts = (__nv_bfloat16*)(sm8 + 34816);     // [128 t][136 c]
    float*         Os  = (float*)sm8;                        // reuse: [128 o][132 t]

    const int tid = threadIdx.x, lane = tid & 31, wid = tid >> 5;
    const int t0 = blockIdx.x * 128, n = blockIdx.y, o0 = blockIdx.z * 128;
    const int g = lane >> 2, tg = lane & 3;

    for (int i = tid; i < 128*32; i += 256) {
        int o = i >> 5, c4 = (i & 31) * 4;
        float4 v = *(const float4*)(wz + (size_t)(o0 + o)*CMID + c4);
        Wzs[o*136 + c4 + 0] = __float2bfloat16(v.x);
        Wzs[o*136 + c4 + 1] = __float2bfloat16(v.y);
        Wzs[o*136 + c4 + 2] = __float2bfloat16(v.z);
        Wzs[o*136 + c4 + 3] = __float2bfloat16(v.w);
    }
    for (int i = tid; i < 128*16; i += 256) {
        int r = i >> 4, ch = i & 15;
        *(uint4*)(Zts + r*136 + ch*8) =
            *(const uint4*)(g_zT + (size_t)(n*HW + t0 + r)*CMID + ch*8);
    }
    __syncthreads();

    float acc[16][4];
#pragma unroll
    for (int j = 0; j < 16; j++)
#pragma unroll
        for (int q = 0; q < 4; q++) acc[j][q] = 0.f;

#pragma unroll
    for (int kk = 0; kk < 8; kk++) {
        uint32_t a0, a1, a2, a3;
        ldsm_x4(a0, a1, a2, a3, Wzs + (wid*16 + (lane & 15))*136 + kk*16 + (lane >> 4)*8);
#pragma unroll
        for (int j = 0; j < 16; j++) {
            uint32_t b0, b1;
            ldsm_x2(b0, b1, Zts + (j*8 + (lane & 7))*136 + kk*16 + ((lane >> 3) & 1)*8);
            mma16816(acc[j], a0, a1, a2, a3, b0, b1);
        }
    }
    __syncthreads();

#pragma unroll
    for (int j = 0; j < 16; j++) {
        int t = j*8 + tg*2;
        Os[(wid*16 + g)*132 + t]         = acc[j][0];
        Os[(wid*16 + g)*132 + t + 1]     = acc[j][1];
        Os[(wid*16 + g + 8)*132 + t]     = acc[j][2];
        Os[(wid*16 + g + 8)*132 + t + 1] = acc[j][3];
    }
    __syncthreads();

    for (int i = tid; i < 128*32; i += 256) {
        int o = i >> 5, t4 = (i & 31) * 4;
        size_t base = (size_t)(n*CIN + o0 + o)*HW + t0 + t4;
        float bb = __ldg(bz + o0 + o);
        float4 xv = *(const float4*)(x + base);
        float4 r;
        r.x = xv.x + bb + Os[o*132 + t4 + 0];
        r.y = xv.y + bb + Os[o*132 + t4 + 1];
        r.z = xv.z + bb + Os[o*132 + t4 + 2];
        r.w = xv.w + bb + Os[o*132 + t4 + 3];
        *(float4*)(out + base) = r;
    }
}

// ---------------- launcher ----------------
extern "C" void kernel_launch(void* const* d_in, const int* in_sizes, int n_in,
                              void* d_out, int out_size)
{
    const float* x  = (const float*)d_in[0];
    const float* wq = (const float*)d_in[1];
    const float* bq = (const float*)d_in[2];
    const float* wk = (const float*)d_in[3];
    const float* bk = (const float*)d_in[4];
    const float* wv = (const float*)d_in[5];
    const float* bv = (const float*)d_in[6];
    const float* wz = (const float*)d_in[7];
    const float* bz = (const float*)d_in[8];
    float* out = (float*)d_out;

    cudaFuncSetAttribute(k_qkv,  cudaFuncAttributeMaxDynamicSharedMemorySize, QKV_SMEM);
    cudaFuncSetAttribute(k_attn, cudaFuncAttributeMaxDynamicSharedMemorySize, ATTN_SMEM);
    cudaFuncSetAttribute(k_out,  cudaFuncAttributeMaxDynamicSharedMemorySize, OUT_SMEM);

    k_qkv <<<dim3(32, 4),    256, QKV_SMEM>>>(x, wq, bq, wk, bk, wv, bv);
    k_attn<<<dim3(32, 4),    256, ATTN_SMEM>>>();
    k_out <<<dim3(32, 4, 2), 256, OUT_SMEM>>>(x, wz, bz, out);
}

// round 6
// speedup vs baseline: 1.1938x; 1.1938x over previous
#include <cuda_runtime.h>
#include <cuda_bf16.h>
#include <cstdint>

#define HW   4096
#define CIN  256
#define CMID 128
#define NB   4

// ---------------- scratch ----------------
__device__ __nv_bfloat16 g_qT[NB*HW*CMID];   // [n][t][c]  (pre-scaled by log2e/64)
__device__ __nv_bfloat16 g_kT[NB*HW*CMID];   // [n][s][c]
__device__ __nv_bfloat16 g_vT[NB*HW*CMID];   // [n][s][c]
__device__ __nv_bfloat16 g_zT[NB*HW*CMID];   // [n][t][c]

// opaque 1 — forces mad.lo.u32 to stay IMAD (fma pipe) instead of IADD3 (alu pipe)
__device__ uint32_t g_one = 1u;

// q pre-scale: log2(e)/64  (softmax exp becomes bare ex2)
#define QSCALE 0.0225421100f

// ---------------- threefry2x32 (JAX partitionable) ----------------
// round add goes to the fma pipe via IMAD(x1 * one + x0); rotate+xor stay alu.
__device__ __forceinline__ uint32_t madd1(uint32_t a, uint32_t c, uint32_t one) {
    uint32_t d;
    asm("mad.lo.u32 %0, %1, %2, %3;" : "=r"(d) : "r"(a), "r"(one), "r"(c));
    return d;   // a*1 + c
}
__device__ __forceinline__ void thf_round(uint32_t& x0, uint32_t& x1, int r, uint32_t one) {
    x0 = madd1(x1, x0, one);
    x1 = __funnelshift_l(x1, x1, r) ^ x0;
}
__device__ __forceinline__ uint32_t thf_bits(uint32_t f, uint32_t one) {
    const uint32_t K1 = 42u;
    const uint32_t K2 = 0x1BD11BDAu ^ 42u;
    uint32_t x0 = 0u, x1 = f + K1;
    thf_round(x0,x1,13,one); thf_round(x0,x1,15,one); thf_round(x0,x1,26,one); thf_round(x0,x1,6,one);
    x0 += K1; x1 += K2 + 1u;
    thf_round(x0,x1,17,one); thf_round(x0,x1,29,one); thf_round(x0,x1,16,one); thf_round(x0,x1,24,one);
    x0 += K2; x1 += 2u;
    thf_round(x0,x1,13,one); thf_round(x0,x1,15,one); thf_round(x0,x1,26,one); thf_round(x0,x1,6,one);
    x1 += K1 + 3u;                      // x0 += K0 (=0)
    thf_round(x0,x1,17,one); thf_round(x0,x1,29,one); thf_round(x0,x1,16,one); thf_round(x0,x1,24,one);
    x0 += K1; x1 += K2 + 4u;
    thf_round(x0,x1,13,one); thf_round(x0,x1,15,one); thf_round(x0,x1,26,one); thf_round(x0,x1,6,one);
    x0 += K2; x1 += 5u;
    return x0 ^ x1;
}
// mask <=> (bits>>9) < 838861  <=>  bits < 838861*512
#define MASK_THRESH 429496832u

__device__ __forceinline__ float ex2f_(float x) {
    float r;
    asm("ex2.approx.f32 %0, %1;\n" : "=f"(r) : "f"(x));
    return r;
}

// ---------------- mma helpers ----------------
__device__ __forceinline__ void cp16(void* dst, const void* src) {
    uint32_t d = (uint32_t)__cvta_generic_to_shared(dst);
    asm volatile("cp.async.cg.shared.global [%0], [%1], 16;\n" :: "r"(d), "l"(src));
}
__device__ __forceinline__ void ldsm_x4(uint32_t& a0, uint32_t& a1, uint32_t& a2, uint32_t& a3, const void* p) {
    uint32_t s = (uint32_t)__cvta_generic_to_shared(p);
    asm volatile("ldmatrix.sync.aligned.m8n8.x4.shared.b16 {%0,%1,%2,%3}, [%4];\n"
                 : "=r"(a0), "=r"(a1), "=r"(a2), "=r"(a3) : "r"(s));
}
__device__ __forceinline__ void ldsm_x2(uint32_t& b0, uint32_t& b1, const void* p) {
    uint32_t s = (uint32_t)__cvta_generic_to_shared(p);
    asm volatile("ldmatrix.sync.aligned.m8n8.x2.shared.b16 {%0,%1}, [%2];\n"
                 : "=r"(b0), "=r"(b1) : "r"(s));
}
__device__ __forceinline__ void ldsm_x2t(uint32_t& b0, uint32_t& b1, const void* p) {
    uint32_t s = (uint32_t)__cvta_generic_to_shared(p);
    asm volatile("ldmatrix.sync.aligned.m8n8.x2.trans.shared.b16 {%0,%1}, [%2];\n"
                 : "=r"(b0), "=r"(b1) : "r"(s));
}
__device__ __forceinline__ void mma16816(float* d, uint32_t a0, uint32_t a1, uint32_t a2, uint32_t a3,
                                         uint32_t b0, uint32_t b1) {
    asm volatile("mma.sync.aligned.m16n8k16.row.col.f32.bf16.bf16.f32 "
                 "{%0,%1,%2,%3}, {%4,%5,%6,%7}, {%8,%9}, {%0,%1,%2,%3};\n"
                 : "+f"(d[0]), "+f"(d[1]), "+f"(d[2]), "+f"(d[3])
                 : "r"(a0), "r"(a1), "r"(a2), "r"(a3), "r"(b0), "r"(b1));
}
__device__ __forceinline__ uint32_t pack_bf2(float lo, float hi) {
    __nv_bfloat162 h = __floats2bfloat162_rn(lo, hi);
    return *(uint32_t*)&h;
}

// ---------------- kernel 1: q/k/v projection (tensor core) ----------------
#define QKV_SMEM 135168
__global__ void __launch_bounds__(256, 1)
k_qkv(const float* __restrict__ x,
      const float* __restrict__ wq, const float* __restrict__ bq,
      const float* __restrict__ wk, const float* __restrict__ bk,
      const float* __restrict__ wv, const float* __restrict__ bv)
{
    extern __shared__ char sm8[];
    __nv_bfloat16* Xs = (__nv_bfloat16*)sm8;              // [128 t][264 c]
    __nv_bfloat16* Ws = (__nv_bfloat16*)(sm8 + 67584);    // [128 o][264 c] / stage [128][136]

    const int tid = threadIdx.x, lane = tid & 31, wid = tid >> 5;
    const int t0 = blockIdx.x * 128, n = blockIdx.y;
    const int g = lane >> 2, tg = lane & 3;

    for (int i = tid; i < 256*32; i += 256) {
        int c = i >> 5, t4 = (i & 31) * 4;
        float4 v = *(const float4*)(x + (size_t)(n*CIN + c)*HW + t0 + t4);
        Xs[(t4+0)*264 + c] = __float2bfloat16(v.x);
        Xs[(t4+1)*264 + c] = __float2bfloat16(v.y);
        Xs[(t4+2)*264 + c] = __float2bfloat16(v.z);
        Xs[(t4+3)*264 + c] = __float2bfloat16(v.w);
    }

#pragma unroll 1
    for (int m = 0; m < 3; m++) {
        const float* wp = (m == 0) ? wq : (m == 1) ? wk : wv;
        const float* bp = (m == 0) ? bq : (m == 1) ? bk : bv;
        const float sc = (m == 0) ? QSCALE : 1.0f;
        __syncthreads();
        for (int i = tid; i < 128*64; i += 256) {
            int o = i >> 6, c4 = (i & 63) * 4;
            float4 v = *(const float4*)(wp + o*CIN + c4);
            Ws[o*264 + c4 + 0] = __float2bfloat16(v.x);
            Ws[o*264 + c4 + 1] = __float2bfloat16(v.y);
            Ws[o*264 + c4 + 2] = __float2bfloat16(v.z);
            Ws[o*264 + c4 + 3] = __float2bfloat16(v.w);
        }
        __syncthreads();

        float acc[16][4];
#pragma unroll
        for (int j = 0; j < 16; j++)
#pragma unroll
            for (int q = 0; q < 4; q++) acc[j][q] = 0.f;

#pragma unroll
        for (int kk = 0; kk < 16; kk++) {
            uint32_t a0, a1, a2, a3;
            ldsm_x4(a0, a1, a2, a3, Xs + (wid*16 + (lane & 15))*264 + kk*16 + (lane >> 4)*8);
#pragma unroll
            for (int j = 0; j < 16; j++) {
                uint32_t b0, b1;
                ldsm_x2(b0, b1, Ws + (j*8 + (lane & 7))*264 + kk*16 + ((lane >> 3) & 1)*8);
                mma16816(acc[j], a0, a1, a2, a3, b0, b1);
            }
        }
        __syncthreads();

        __nv_bfloat16* Tb = Ws;   // [128][136]
#pragma unroll
        for (int j = 0; j < 16; j++) {
            int o = j*8 + tg*2;
            float b0 = __ldg(bp + o), b1 = __ldg(bp + o + 1);
            Tb[(wid*16 + g)*136 + o]         = __float2bfloat16((acc[j][0] + b0) * sc);
            Tb[(wid*16 + g)*136 + o + 1]     = __float2bfloat16((acc[j][1] + b1) * sc);
            Tb[(wid*16 + g + 8)*136 + o]     = __float2bfloat16((acc[j][2] + b0) * sc);
            Tb[(wid*16 + g + 8)*136 + o + 1] = __float2bfloat16((acc[j][3] + b1) * sc);
        }
        __syncthreads();
        __nv_bfloat16* gdst = (m == 0) ? g_qT : (m == 1) ? g_kT : g_vT;
        for (int i = tid; i < 128*16; i += 256) {
            int r = i >> 4, ch = i & 15;
            *(uint4*)(gdst + (size_t)(n*HW + t0 + r)*CMID + ch*8) =
                *(const uint4*)(Tb + r*136 + ch*8);
        }
    }
}

// ---------------- kernel 2: tensor-core attention, s-tile 128 ----------------
#define ATTN_SMEM 174080
__global__ void __launch_bounds__(256, 1)
k_attn()
{
    extern __shared__ char sm8[];
    __nv_bfloat16* Qs  = (__nv_bfloat16*)sm8;               // [128][136]
    __nv_bfloat16* Kb0 = (__nv_bfloat16*)(sm8 + 34816);
    __nv_bfloat16* Kb1 = (__nv_bfloat16*)(sm8 + 69632);
    __nv_bfloat16* Vb0 = (__nv_bfloat16*)(sm8 + 104448);
    __nv_bfloat16* Vb1 = (__nv_bfloat16*)(sm8 + 139264);

    const int tid = threadIdx.x, lane = tid & 31, wid = tid >> 5;
    const int t0 = blockIdx.x * 128, n = blockIdx.y;
    const int g = lane >> 2, tg = lane & 3;
    const uint32_t one = g_one;

    for (int i = tid; i < 128*16; i += 256) {
        int r = i >> 4, ch = i & 15;
        size_t go = (size_t)(n*HW + r)*CMID + ch*8;
        cp16(Qs  + r*136 + ch*8, g_qT + (size_t)(n*HW + t0 + r)*CMID + ch*8);
        cp16(Kb0 + r*136 + ch*8, g_kT + go);
        cp16(Vb0 + r*136 + ch*8, g_vT + go);
    }
    asm volatile("cp.async.commit_group;\n");

    float Z[16][4];
#pragma unroll
    for (int jc = 0; jc < 16; jc++)
#pragma unroll
        for (int q = 0; q < 4; q++) Z[jc][q] = 0.f;
    float dsum0 = 0.f, dsum1 = 0.f;

#pragma unroll 1
    for (int it = 0; it < 32; it++) {
        const __nv_bfloat16* K_ = (it & 1) ? Kb1 : Kb0;
        const __nv_bfloat16* V_ = (it & 1) ? Vb1 : Vb0;
        if (it + 1 < 32) {
            __nv_bfloat16* Kn = ((it+1) & 1) ? Kb1 : Kb0;
            __nv_bfloat16* Vn = ((it+1) & 1) ? Vb1 : Vb0;
            int s0n = (it + 1) * 128;
            for (int i = tid; i < 128*16; i += 256) {
                int r = i >> 4, ch = i & 15;
                size_t go = (size_t)(n*HW + s0n + r)*CMID + ch*8;
                cp16(Kn + r*136 + ch*8, g_kT + go);
                cp16(Vn + r*136 + ch*8, g_vT + go);
            }
            asm volatile("cp.async.commit_group;\n");
            asm volatile("cp.async.wait_group 1;\n");
        } else {
            asm volatile("cp.async.wait_group 0;\n");
        }
        __syncthreads();

        // ---- GEMM1: S[16t x 128s] ----
        float S[16][4];
#pragma unroll
        for (int j = 0; j < 16; j++)
#pragma unroll
            for (int q = 0; q < 4; q++) S[j][q] = 0.f;
#pragma unroll
        for (int kk = 0; kk < 8; kk++) {
            uint32_t a0, a1, a2, a3;
            ldsm_x4(a0, a1, a2, a3, Qs + (wid*16 + (lane & 15))*136 + kk*16 + (lane >> 4)*8);
#pragma unroll
            for (int j = 0; j < 16; j++) {
                uint32_t b0, b1;
                ldsm_x2(b0, b1, K_ + (j*8 + (lane & 7))*136 + kk*16 + ((lane >> 3) & 1)*8);
                mma16816(S[j], a0, a1, a2, a3, b0, b1);
            }
        }

        // ---- mask (threefry, adds on fma pipe) + ex2 ----
        const int s0 = it * 128;
        const uint32_t fb0 = ((uint32_t)n << 24) + (uint32_t)(t0 + wid*16 + g)*4096u
                           + (uint32_t)(s0 + tg*2);
        const uint32_t fb1 = fb0 + 8u*4096u;
#pragma unroll
        for (int j = 0; j < 16; j++) {
            uint32_t f0 = fb0 + (uint32_t)(j*8);
            uint32_t f1 = fb1 + (uint32_t)(j*8);
            S[j][0] = (thf_bits(f0,    one) < MASK_THRESH) ? 0.f : ex2f_(S[j][0]);
            S[j][1] = (thf_bits(f0+1u, one) < MASK_THRESH) ? 0.f : ex2f_(S[j][1]);
            S[j][2] = (thf_bits(f1,    one) < MASK_THRESH) ? 0.f : ex2f_(S[j][2]);
            S[j][3] = (thf_bits(f1+1u, one) < MASK_THRESH) ? 0.f : ex2f_(S[j][3]);
            dsum0 += S[j][0] + S[j][1];
            dsum1 += S[j][2] + S[j][3];
        }

        // ---- GEMM2: Z[16t x 128c] += P * V ----
#pragma unroll
        for (int m = 0; m < 8; m++) {
            uint32_t pa0 = pack_bf2(S[2*m][0],   S[2*m][1]);
            uint32_t pa1 = pack_bf2(S[2*m][2],   S[2*m][3]);
            uint32_t pa2 = pack_bf2(S[2*m+1][0], S[2*m+1][1]);
            uint32_t pa3 = pack_bf2(S[2*m+1][2], S[2*m+1][3]);
#pragma unroll
            for (int jc = 0; jc < 16; jc++) {
                uint32_t b0, b1;
                ldsm_x2t(b0, b1, V_ + (m*16 + (lane & 7) + ((lane >> 3) & 1)*8)*136 + jc*8);
                mma16816(Z[jc], pa0, pa1, pa2, pa3, b0, b1);
            }
        }
        __syncthreads();
    }

    // ---- row denominators (quad reduce) ----
    dsum0 += __shfl_xor_sync(0xffffffffu, dsum0, 1);
    dsum0 += __shfl_xor_sync(0xffffffffu, dsum0, 2);
    dsum1 += __shfl_xor_sync(0xffffffffu, dsum1, 1);
    dsum1 += __shfl_xor_sync(0xffffffffu, dsum1, 2);
    const float inv0 = 1.f / dsum0, inv1 = 1.f / dsum1;

    // ---- stage zT[t][c] bf16, coalesced store ----
    __nv_bfloat16* Tb = Kb0;   // [128][136]
#pragma unroll
    for (int jc = 0; jc < 16; jc++) {
        int c = jc*8 + tg*2;
        Tb[(wid*16 + g)*136 + c]         = __float2bfloat16(Z[jc][0] * inv0);
        Tb[(wid*16 + g)*136 + c + 1]     = __float2bfloat16(Z[jc][1] * inv0);
        Tb[(wid*16 + g + 8)*136 + c]     = __float2bfloat16(Z[jc][2] * inv1);
        Tb[(wid*16 + g + 8)*136 + c + 1] = __float2bfloat16(Z[jc][3] * inv1);
    }
    __syncthreads();
    for (int i = tid; i < 128*16; i += 256) {
        int r = i >> 4, ch = i & 15;
        *(uint4*)(g_zT + (size_t)(n*HW + t0 + r)*CMID + ch*8) =
            *(const uint4*)(Tb + r*136 + ch*8);
    }
}

// ---------------- kernel 3: output projection + residual (tensor core) ----------------
#define OUT_SMEM 69632
__global__ void __launch_bounds__(256, 1)
k_out(const float* __restrict__ x, const float* __restrict__ wz,
      const float* __restrict__ bz, float* __restrict__ out)
{
    extern __shared__ char sm8[];
    __nv_bfloat16* Wzs = (__nv_bfloat16*)sm8;               // [128 o][136 c]
    __nv_bfloat16* Zts = (__nv_bfloat16*)(sm8 + 34816);     // [128 t][136 c]
    float*         Os  = (float*)sm8;                        // reuse: [128 o][132 t]

    const int tid = threadIdx.x, lane = tid & 31, wid = tid >> 5;
    const int t0 = blockIdx.x * 128, n = blockIdx.y, o0 = blockIdx.z * 128;
    const int g = lane >> 2, tg = lane & 3;

    for (int i = tid; i < 128*32; i += 256) {
        int o = i >> 5, c4 = (i & 31) * 4;
        float4 v = *(const float4*)(wz + (size_t)(o0 + o)*CMID + c4);
        Wzs[o*136 + c4 + 0] = __float2bfloat16(v.x);
        Wzs[o*136 + c4 + 1] = __float2bfloat16(v.y);
        Wzs[o*136 + c4 + 2] = __float2bfloat16(v.z);
        Wzs[o*136 + c4 + 3] = __float2bfloat16(v.w);
    }
    for (int i = tid; i < 128*16; i += 256) {
        int r = i >> 4, ch = i & 15;
        *(uint4*)(Zts + r*136 + ch*8) =
            *(const uint4*)(g_zT + (size_t)(n*HW + t0 + r)*CMID + ch*8);
    }
    __syncthreads();

    float acc[16][4];
#pragma unroll
    for (int j = 0; j < 16; j++)
#pragma unroll
        for (int q = 0; q < 4; q++) acc[j][q] = 0.f;

#pragma unroll
    for (int kk = 0; kk < 8; kk++) {
        uint32_t a0, a1, a2, a3;
        ldsm_x4(a0, a1, a2, a3, Wzs + (wid*16 + (lane & 15))*136 + kk*16 + (lane >> 4)*8);
#pragma unroll
        for (int j = 0; j < 16; j++) {
            uint32_t b0, b1;
            ldsm_x2(b0, b1, Zts + (j*8 + (lane & 7))*136 + kk*16 + ((lane >> 3) & 1)*8);
            mma16816(acc[j], a0, a1, a2, a3, b0, b1);
        }
    }
    __syncthreads();

#pragma unroll
    for (int j = 0; j < 16; j++) {
        int t = j*8 + tg*2;
        Os[(wid*16 + g)*132 + t]         = acc[j][0];
        Os[(wid*16 + g)*132 + t + 1]     = acc[j][1];
        Os[(wid*16 + g + 8)*132 + t]     = acc[j][2];
        Os[(wid*16 + g + 8)*132 + t + 1] = acc[j][3];
    }
    __syncthreads();

    for (int i = tid; i < 128*32; i += 256) {
        int o = i >> 5, t4 = (i & 31) * 4;
        size_t base = (size_t)(n*CIN + o0 + o)*HW + t0 + t4;
        float bb = __ldg(bz + o0 + o);
        float4 xv = *(const float4*)(x + base);
        float4 r;
        r.x = xv.x + bb + Os[o*132 + t4 + 0];
        r.y = xv.y + bb + Os[o*132 + t4 + 1];
        r.z = xv.z + bb + Os[o*132 + t4 + 2];
        r.w = xv.w + bb + Os[o*132 + t4 + 3];
        *(float4*)(out + base) = r;
    }
}

// ---------------- launcher ----------------
extern "C" void kernel_launch(void* const* d_in, const int* in_sizes, int n_in,
                              void* d_out, int out_size)
{
    const float* x  = (const float*)d_in[0];
    const float* wq = (const float*)d_in[1];
    const float* bq = (const float*)d_in[2];
    const float* wk = (const float*)d_in[3];
    const float* bk = (const float*)d_in[4];
    const float* wv = (const float*)d_in[5];
    const float* bv = (const float*)d_in[6];
    const float* wz = (const float*)d_in[7];
    const float* bz = (const float*)d_in[8];
    float* out = (float*)d_out;

    cudaFuncSetAttribute(k_qkv,  cudaFuncAttributeMaxDynamicSharedMemorySize, QKV_SMEM);
    cudaFuncSetAttribute(k_attn, cudaFuncAttributeMaxDynamicSharedMemorySize, ATTN_SMEM);
    cudaFuncSetAttribute(k_out,  cudaFuncAttributeMaxDynamicSharedMemorySize, OUT_SMEM);

    k_qkv <<<dim3(32, 4),    256, QKV_SMEM>>>(x, wq, bq, wk, bk, wv, bv);
    k_attn<<<dim3(32, 4),    256, ATTN_SMEM>>>();
    k_out <<<dim3(32, 4, 2), 256, OUT_SMEM>>>(x, wz, bz, out);
}

// round 8
// speedup vs baseline: 1.2273x; 1.0280x over previous
#include <cuda_runtime.h>
#include <cuda_bf16.h>
#include <cstdint>

#define HW   4096
#define CIN  256
#define CMID 128
#define NB   4

// ---------------- scratch ----------------
__device__ __nv_bfloat16 g_qT[NB*HW*CMID];   // [n][t][c]  (pre-scaled by log2e/64)
__device__ __nv_bfloat16 g_kT[NB*HW*CMID];   // [n][s][c]
__device__ __nv_bfloat16 g_vT[NB*HW*CMID];   // [n][s][c]
__device__ __nv_bfloat16 g_zT[NB*HW*CMID];   // [n][t][c]

// q pre-scale: log2(e)/64
#define QSCALE 0.0225421100f

// ---------------- threefry2x32 (JAX partitionable) ----------------
__device__ __forceinline__ uint32_t thf_bits(uint32_t f) {
    const uint32_t K1 = 42u;
    const uint32_t K2 = 0x1BD11BDAu ^ 42u;
    uint32_t x0 = 0u, x1 = f + K1;
#define THF_R(r) { x0 += x1; x1 = __funnelshift_l(x1, x1, (r)); x1 ^= x0; }
    THF_R(13) THF_R(15) THF_R(26) THF_R(6)   x0 += K1; x1 += K2 + 1u;
    THF_R(17) THF_R(29) THF_R(16) THF_R(24)  x0 += K2; x1 += 2u;
    THF_R(13) THF_R(15) THF_R(26) THF_R(6)   x1 += K1 + 3u;
    THF_R(17) THF_R(29) THF_R(16) THF_R(24)  x0 += K1; x1 += K2 + 4u;
    THF_R(13) THF_R(15) THF_R(26) THF_R(6)   x0 += K2; x1 += 5u;
#undef THF_R
    return x0 ^ x1;
}
// mask <=> (bits>>9) < 838861  <=>  bits < 838861*512
#define MASK_THRESH 429496832u

__device__ __forceinline__ float ex2f_(float x) {
    float r;
    asm("ex2.approx.f32 %0, %1;\n" : "=f"(r) : "f"(x));
    return r;
}

// ---------------- mma helpers ----------------
__device__ __forceinline__ void cp16(void* dst, const void* src) {
    uint32_t d = (uint32_t)__cvta_generic_to_shared(dst);
    asm volatile("cp.async.cg.shared.global [%0], [%1], 16;\n" :: "r"(d), "l"(src));
}
__device__ __forceinline__ void ldsm_x4(uint32_t& a0, uint32_t& a1, uint32_t& a2, uint32_t& a3, const void* p) {
    uint32_t s = (uint32_t)__cvta_generic_to_shared(p);
    asm volatile("ldmatrix.sync.aligned.m8n8.x4.shared.b16 {%0,%1,%2,%3}, [%4];\n"
                 : "=r"(a0), "=r"(a1), "=r"(a2), "=r"(a3) : "r"(s));
}
__device__ __forceinline__ void ldsm_x2(uint32_t& b0, uint32_t& b1, const void* p) {
    uint32_t s = (uint32_t)__cvta_generic_to_shared(p);
    asm volatile("ldmatrix.sync.aligned.m8n8.x2.shared.b16 {%0,%1}, [%2];\n"
                 : "=r"(b0), "=r"(b1) : "r"(s));
}
__device__ __forceinline__ void ldsm_x2t(uint32_t& b0, uint32_t& b1, const void* p) {
    uint32_t s = (uint32_t)__cvta_generic_to_shared(p);
    asm volatile("ldmatrix.sync.aligned.m8n8.x2.trans.shared.b16 {%0,%1}, [%2];\n"
                 : "=r"(b0), "=r"(b1) : "r"(s));
}
__device__ __forceinline__ void mma16816(float* d, uint32_t a0, uint32_t a1, uint32_t a2, uint32_t a3,
                                         uint32_t b0, uint32_t b1) {
    asm volatile("mma.sync.aligned.m16n8k16.row.col.f32.bf16.bf16.f32 "
                 "{%0,%1,%2,%3}, {%4,%5,%6,%7}, {%8,%9}, {%0,%1,%2,%3};\n"
                 : "+f"(d[0]), "+f"(d[1]), "+f"(d[2]), "+f"(d[3])
                 : "r"(a0), "r"(a1), "r"(a2), "r"(a3), "r"(b0), "r"(b1));
}
__device__ __forceinline__ uint32_t pack_bf2(float lo, float hi) {
    __nv_bfloat162 h = __floats2bfloat162_rn(lo, hi);
    return *(uint32_t*)&h;
}

// ---------------- kernel 1: q/k/v projection, t-tile 64, 128 threads ----------------
// grid (64 t, 4 n), 2 CTAs/SM
#define QKV_SMEM 101376
__global__ void __launch_bounds__(128, 2)
k_qkv(const float* __restrict__ x,
      const float* __restrict__ wq, const float* __restrict__ bq,
      const float* __restrict__ wk, const float* __restrict__ bk,
      const float* __restrict__ wv, const float* __restrict__ bv)
{
    extern __shared__ char sm8[];
    __nv_bfloat16* Xs = (__nv_bfloat16*)sm8;              // [64 t][264 c]
    __nv_bfloat16* Ws = (__nv_bfloat16*)(sm8 + 33792);    // [128 o][264 c] / stage [64][136]

    const int tid = threadIdx.x, lane = tid & 31, wid = tid >> 5;
    const int t0 = blockIdx.x * 64, n = blockIdx.y;
    const int g = lane >> 2, tg = lane & 3;

    // x [256 c][64 t] fp32 -> Xs[t][c] bf16
    for (int i = tid; i < 256*16; i += 128) {
        int c = i >> 4, t4 = (i & 15) * 4;
        float4 v = *(const float4*)(x + (size_t)(n*CIN + c)*HW + t0 + t4);
        Xs[(t4+0)*264 + c] = __float2bfloat16(v.x);
        Xs[(t4+1)*264 + c] = __float2bfloat16(v.y);
        Xs[(t4+2)*264 + c] = __float2bfloat16(v.z);
        Xs[(t4+3)*264 + c] = __float2bfloat16(v.w);
    }

#pragma unroll 1
    for (int m = 0; m < 3; m++) {
        const float* wp = (m == 0) ? wq : (m == 1) ? wk : wv;
        const float* bp = (m == 0) ? bq : (m == 1) ? bk : bv;
        const float sc = (m == 0) ? QSCALE : 1.0f;
        __syncthreads();
        for (int i = tid; i < 128*64; i += 128) {
            int o = i >> 6, c4 = (i & 63) * 4;
            float4 v = *(const float4*)(wp + o*CIN + c4);
            Ws[o*264 + c4 + 0] = __float2bfloat16(v.x);
            Ws[o*264 + c4 + 1] = __float2bfloat16(v.y);
            Ws[o*264 + c4 + 2] = __float2bfloat16(v.z);
            Ws[o*264 + c4 + 3] = __float2bfloat16(v.w);
        }
        __syncthreads();

        float acc[16][4];
#pragma unroll
        for (int j = 0; j < 16; j++)
#pragma unroll
            for (int q = 0; q < 4; q++) acc[j][q] = 0.f;

#pragma unroll
        for (int kk = 0; kk < 16; kk++) {
            uint32_t a0, a1, a2, a3;
            ldsm_x4(a0, a1, a2, a3, Xs + (wid*16 + (lane & 15))*264 + kk*16 + (lane >> 4)*8);
#pragma unroll
            for (int j = 0; j < 16; j++) {
                uint32_t b0, b1;
                ldsm_x2(b0, b1, Ws + (j*8 + (lane & 7))*264 + kk*16 + ((lane >> 3) & 1)*8);
                mma16816(acc[j], a0, a1, a2, a3, b0, b1);
            }
        }
        __syncthreads();

        __nv_bfloat16* Tb = Ws;   // [64][136]
#pragma unroll
        for (int j = 0; j < 16; j++) {
            int o = j*8 + tg*2;
            float b0 = __ldg(bp + o), b1 = __ldg(bp + o + 1);
            Tb[(wid*16 + g)*136 + o]         = __float2bfloat16((acc[j][0] + b0) * sc);
            Tb[(wid*16 + g)*136 + o + 1]     = __float2bfloat16((acc[j][1] + b1) * sc);
            Tb[(wid*16 + g + 8)*136 + o]     = __float2bfloat16((acc[j][2] + b0) * sc);
            Tb[(wid*16 + g + 8)*136 + o + 1] = __float2bfloat16((acc[j][3] + b1) * sc);
        }
        __syncthreads();
        __nv_bfloat16* gdst = (m == 0) ? g_qT : (m == 1) ? g_kT : g_vT;
        for (int i = tid; i < 64*16; i += 128) {
            int r = i >> 4, ch = i & 15;
            *(uint4*)(gdst + (size_t)(n*HW + t0 + r)*CMID + ch*8) =
                *(const uint4*)(Tb + r*136 + ch*8);
        }
    }
}

// ---------------- kernel 2: attention, 512 threads (16 warps = 4/SMSP) ----------------
// warps: tgrp = wid&7 (16 t-rows each), half = wid>>3 (s-half in GEMM1, c-half in GEMM2)
#define ATTN_SMEM 209408
__global__ void __launch_bounds__(512, 1)
k_attn()
{
    extern __shared__ char sm8[];
    __nv_bfloat16* Qs  = (__nv_bfloat16*)sm8;               // [128][136]
    __nv_bfloat16* Kb0 = (__nv_bfloat16*)(sm8 + 34816);
    __nv_bfloat16* Kb1 = (__nv_bfloat16*)(sm8 + 69632);
    __nv_bfloat16* Vb0 = (__nv_bfloat16*)(sm8 + 104448);
    __nv_bfloat16* Vb1 = (__nv_bfloat16*)(sm8 + 139264);
    __nv_bfloat16* Ps  = (__nv_bfloat16*)(sm8 + 174080);    // [128 t][136 s]
    float*         dsh = (float*)(sm8 + 208896);            // [128]

    const int tid = threadIdx.x, lane = tid & 31, wid = tid >> 5;
    const int tgrp = wid & 7, half = wid >> 3;
    const int t0 = blockIdx.x * 128, n = blockIdx.y;
    const int g = lane >> 2, tg = lane & 3;

    if (tid < 128) dsh[tid] = 0.f;

    for (int i = tid; i < 128*16; i += 512) {
        int r = i >> 4, ch = i & 15;
        size_t go = (size_t)(n*HW + r)*CMID + ch*8;
        cp16(Qs  + r*136 + ch*8, g_qT + (size_t)(n*HW + t0 + r)*CMID + ch*8);
        cp16(Kb0 + r*136 + ch*8, g_kT + go);
        cp16(Vb0 + r*136 + ch*8, g_vT + go);
    }
    asm volatile("cp.async.commit_group;\n");

    float Z[8][4];
#pragma unroll
    for (int jc = 0; jc < 8; jc++)
#pragma unroll
        for (int q = 0; q < 4; q++) Z[jc][q] = 0.f;
    float dsum0 = 0.f, dsum1 = 0.f;

#pragma unroll 1
    for (int it = 0; it < 32; it++) {
        const __nv_bfloat16* K_ = (it & 1) ? Kb1 : Kb0;
        const __nv_bfloat16* V_ = (it & 1) ? Vb1 : Vb0;
        if (it + 1 < 32) {
            __nv_bfloat16* Kn = ((it+1) & 1) ? Kb1 : Kb0;
            __nv_bfloat16* Vn = ((it+1) & 1) ? Vb1 : Vb0;
            int s0n = (it + 1) * 128;
            for (int i = tid; i < 128*16; i += 512) {
                int r = i >> 4, ch = i & 15;
                size_t go = (size_t)(n*HW + s0n + r)*CMID + ch*8;
                cp16(Kn + r*136 + ch*8, g_kT + go);
                cp16(Vn + r*136 + ch*8, g_vT + go);
            }
            asm volatile("cp.async.commit_group;\n");
            asm volatile("cp.async.wait_group 1;\n");
        } else {
            asm volatile("cp.async.wait_group 0;\n");
        }
        __syncthreads();   // K/V ready; all warps done reading Ps of prev iter

        // ---- GEMM1: S[16t x 64s] (this warp's s-half) ----
        float S[8][4];
#pragma unroll
        for (int j = 0; j < 8; j++)
#pragma unroll
            for (int q = 0; q < 4; q++) S[j][q] = 0.f;
#pragma unroll
        for (int kk = 0; kk < 8; kk++) {
            uint32_t a0, a1, a2, a3;
            ldsm_x4(a0, a1, a2, a3, Qs + (tgrp*16 + (lane & 15))*136 + kk*16 + (lane >> 4)*8);
#pragma unroll
            for (int j = 0; j < 8; j++) {
                uint32_t b0, b1;
                ldsm_x2(b0, b1, K_ + (half*64 + j*8 + (lane & 7))*136 + kk*16 + ((lane >> 3) & 1)*8);
                mma16816(S[j], a0, a1, a2, a3, b0, b1);
            }
        }

        // ---- mask (threefry) + ex2, stage P[t][s] bf16 ----
        const int s0 = it * 128;
        const int trow = t0 + tgrp*16 + g;
        const int scol0 = s0 + half*64 + tg*2;
        const uint32_t fb0 = ((uint32_t)n << 24) + (uint32_t)trow*4096u + (uint32_t)scol0;
        const uint32_t fb1 = fb0 + 8u*4096u;
#pragma unroll
        for (int j = 0; j < 8; j++) {
            uint32_t f0 = fb0 + (uint32_t)(j*8);
            uint32_t f1 = fb1 + (uint32_t)(j*8);
            S[j][0] = (thf_bits(f0)    < MASK_THRESH) ? 0.f : ex2f_(S[j][0]);
            S[j][1] = (thf_bits(f0+1u) < MASK_THRESH) ? 0.f : ex2f_(S[j][1]);
            S[j][2] = (thf_bits(f1)    < MASK_THRESH) ? 0.f : ex2f_(S[j][2]);
            S[j][3] = (thf_bits(f1+1u) < MASK_THRESH) ? 0.f : ex2f_(S[j][3]);
            dsum0 += S[j][0] + S[j][1];
            dsum1 += S[j][2] + S[j][3];
            int col = half*64 + tg*2 + j*8;
            *(uint32_t*)(Ps + (tgrp*16 + g)*136 + col)     = pack_bf2(S[j][0], S[j][1]);
            *(uint32_t*)(Ps + (tgrp*16 + g + 8)*136 + col) = pack_bf2(S[j][2], S[j][3]);
        }
        __syncthreads();   // P complete

        // ---- GEMM2: Z[16t x 64c] (this warp's c-half) += P * V ----
#pragma unroll
        for (int kk = 0; kk < 8; kk++) {
            uint32_t a0, a1, a2, a3;
            ldsm_x4(a0, a1, a2, a3, Ps + (tgrp*16 + (lane & 15))*136 + kk*16 + (lane >> 4)*8);
#pragma unroll
            for (int jc = 0; jc < 8; jc++) {
                uint32_t b0, b1;
                ldsm_x2t(b0, b1, V_ + (kk*16 + (lane & 7) + ((lane >> 3) & 1)*8)*136 + half*64 + jc*8);
                mma16816(Z[jc], a0, a1, a2, a3, b0, b1);
            }
        }
    }

    // ---- row denominators: quad reduce + cross-s-half combine via smem ----
    dsum0 += __shfl_xor_sync(0xffffffffu, dsum0, 1);
    dsum0 += __shfl_xor_sync(0xffffffffu, dsum0, 2);
    dsum1 += __shfl_xor_sync(0xffffffffu, dsum1, 1);
    dsum1 += __shfl_xor_sync(0xffffffffu, dsum1, 2);
    if (tg == 0) {
        atomicAdd(&dsh[tgrp*16 + g], dsum0);
        atomicAdd(&dsh[tgrp*16 + g + 8], dsum1);
    }
    __syncthreads();
    const float inv0 = 1.f / dsh[tgrp*16 + g];
    const float inv1 = 1.f / dsh[tgrp*16 + g + 8];

    // ---- stage zT[t][c] bf16 (Ps reused), coalesced store ----
    __nv_bfloat16* Tb = Ps;   // [128][136]
#pragma unroll
    for (int jc = 0; jc < 8; jc++) {
        int c = half*64 + jc*8 + tg*2;
        *(uint32_t*)(Tb + (tgrp*16 + g)*136 + c)     = pack_bf2(Z[jc][0]*inv0, Z[jc][1]*inv0);
        *(uint32_t*)(Tb + (tgrp*16 + g + 8)*136 + c) = pack_bf2(Z[jc][2]*inv1, Z[jc][3]*inv1);
    }
    __syncthreads();
    for (int i = tid; i < 128*16; i += 512) {
        int r = i >> 4, ch = i & 15;
        *(uint4*)(g_zT + (size_t)(n*HW + t0 + r)*CMID + ch*8) =
            *(const uint4*)(Tb + r*136 + ch*8);
    }
}

// ---------------- kernel 3: output projection + residual (tensor core) ----------------
#define OUT_SMEM 69632
__global__ void __launch_bounds__(256, 1)
k_out(const float* __restrict__ x, const float* __restrict__ wz,
      const float* __restrict__ bz, float* __restrict__ out)
{
    extern __shared__ char sm8[];
    __nv_bfloat16* Wzs = (__nv_bfloat16*)sm8;               // [128 o][136 c]
    __nv_bfloat16* Zts = (__nv_bfloat16*)(sm8 + 34816);     // [128 t][136 c]
    float*         Os  = (float*)sm8;                        // reuse: [128 o][132 t]

    const int tid = threadIdx.x, lane = tid & 31, wid = tid >> 5;
    const int t0 = blockIdx.x * 128, n = blockIdx.y, o0 = blockIdx.z * 128;
    const int g = lane >> 2, tg = lane & 3;

    for (int i = tid; i < 128*32; i += 256) {
        int o = i >> 5, c4 = (i & 31) * 4;
        float4 v = *(const float4*)(wz + (size_t)(o0 + o)*CMID + c4);
        Wzs[o*136 + c4 + 0] = __float2bfloat16(v.x);
        Wzs[o*136 + c4 + 1] = __float2bfloat16(v.y);
        Wzs[o*136 + c4 + 2] = __float2bfloat16(v.z);
        Wzs[o*136 + c4 + 3] = __float2bfloat16(v.w);
    }
    for (int i = tid; i < 128*16; i += 256) {
        int r = i >> 4, ch = i & 15;
        *(uint4*)(Zts + r*136 + ch*8) =
            *(const uint4*)(g_zT + (size_t)(n*HW + t0 + r)*CMID + ch*8);
    }
    __syncthreads();

    float acc[16][4];
#pragma unroll
    for (int j = 0; j < 16; j++)
#pragma unroll
        for (int q = 0; q < 4; q++) acc[j][q] = 0.f;

#pragma unroll
    for (int kk = 0; kk < 8; kk++) {
        uint32_t a0, a1, a2, a3;
        ldsm_x4(a0, a1, a2, a3, Wzs + (wid*16 + (lane & 15))*136 + kk*16 + (lane >> 4)*8);
#pragma unroll
        for (int j = 0; j < 16; j++) {
            uint32_t b0, b1;
            ldsm_x2(b0, b1, Zts + (j*8 + (lane & 7))*136 + kk*16 + ((lane >> 3) & 1)*8);
            mma16816(acc[j], a0, a1, a2, a3, b0, b1);
        }
    }
    __syncthreads();

#pragma unroll
    for (int j = 0; j < 16; j++) {
        int t = j*8 + tg*2;
        Os[(wid*16 + g)*132 + t]         = acc[j][0];
        Os[(wid*16 + g)*132 + t + 1]     = acc[j][1];
        Os[(wid*16 + g + 8)*132 + t]     = acc[j][2];
        Os[(wid*16 + g + 8)*132 + t + 1] = acc[j][3];
    }
    __syncthreads();

    for (int i = tid; i < 128*32; i += 256) {
        int o = i >> 5, t4 = (i & 31) * 4;
        size_t base = (size_t)(n*CIN + o0 + o)*HW + t0 + t4;
        float bb = __ldg(bz + o0 + o);
        float4 xv = *(const float4*)(x + base);
        float4 r;
        r.x = xv.x + bb + Os[o*132 + t4 + 0];
        r.y = xv.y + bb + Os[o*132 + t4 + 1];
        r.z = xv.z + bb + Os[o*132 + t4 + 2];
        r.w = xv.w + bb + Os[o*132 + t4 + 3];
        *(float4*)(out + base) = r;
    }
}

// ---------------- launcher ----------------
extern "C" void kernel_launch(void* const* d_in, const int* in_sizes, int n_in,
                              void* d_out, int out_size)
{
    const float* x  = (const float*)d_in[0];
    const float* wq = (const float*)d_in[1];
    const float* bq = (const float*)d_in[2];
    const float* wk = (const float*)d_in[3];
    const float* bk = (const float*)d_in[4];
    const float* wv = (const float*)d_in[5];
    const float* bv = (const float*)d_in[6];
    const float* wz = (const float*)d_in[7];
    const float* bz = (const float*)d_in[8];
    float* out = (float*)d_out;

    cudaFuncSetAttribute(k_qkv,  cudaFuncAttributeMaxDynamicSharedMemorySize, QKV_SMEM);
    cudaFuncSetAttribute(k_attn, cudaFuncAttributeMaxDynamicSharedMemorySize, ATTN_SMEM);
    cudaFuncSetAttribute(k_out,  cudaFuncAttributeMaxDynamicSharedMemorySize, OUT_SMEM);

    k_qkv <<<dim3(64, 4),    128, QKV_SMEM>>>(x, wq, bq, wk, bk, wv, bv);
    k_attn<<<dim3(32, 4),    512, ATTN_SMEM>>>();
    k_out <<<dim3(32, 4, 2), 256, OUT_SMEM>>>(x, wz, bz, out);
}

// round 9
// speedup vs baseline: 1.2417x; 1.0117x over previous
#include <cuda_runtime.h>
#include <cuda_bf16.h>
#include <cstdint>

#define HW   4096
#define CIN  256
#define CMID 128
#define NB   4

// ---------------- scratch ----------------
__device__ __nv_bfloat16 g_qT[NB*HW*CMID];   // [n][t][c]  (pre-scaled by log2e/64)
__device__ __nv_bfloat16 g_kT[NB*HW*CMID];   // [n][s][c]
__device__ __nv_bfloat16 g_vT[NB*HW*CMID];   // [n][s][c]
__device__ __nv_bfloat16 g_zT[NB*HW*CMID];   // [n][t][c]

// q pre-scale: log2(e)/64
#define QSCALE 0.0225421100f

// ---------------- threefry2x32 (JAX partitionable) ----------------
__device__ __forceinline__ uint32_t thf_bits(uint32_t f) {
    const uint32_t K1 = 42u;
    const uint32_t K2 = 0x1BD11BDAu ^ 42u;
    uint32_t x0 = 0u, x1 = f + K1;
#define THF_R(r) { x0 += x1; x1 = __funnelshift_l(x1, x1, (r)); x1 ^= x0; }
    THF_R(13) THF_R(15) THF_R(26) THF_R(6)   x0 += K1; x1 += K2 + 1u;
    THF_R(17) THF_R(29) THF_R(16) THF_R(24)  x0 += K2; x1 += 2u;
    THF_R(13) THF_R(15) THF_R(26) THF_R(6)   x1 += K1 + 3u;
    THF_R(17) THF_R(29) THF_R(16) THF_R(24)  x0 += K1; x1 += K2 + 4u;
    THF_R(13) THF_R(15) THF_R(26) THF_R(6)   x0 += K2; x1 += 5u;
#undef THF_R
    return x0 ^ x1;
}
// mask <=> (bits>>9) < 838861  <=>  bits < 838861*512
#define MASK_THRESH 429496832u

__device__ __forceinline__ float ex2f_(float x) {
    float r;
    asm("ex2.approx.f32 %0, %1;\n" : "=f"(r) : "f"(x));
    return r;
}

// ---------------- mma helpers ----------------
__device__ __forceinline__ void cp16(void* dst, const void* src) {
    uint32_t d = (uint32_t)__cvta_generic_to_shared(dst);
    asm volatile("cp.async.cg.shared.global [%0], [%1], 16;\n" :: "r"(d), "l"(src));
}
__device__ __forceinline__ void ldsm_x4(uint32_t& a0, uint32_t& a1, uint32_t& a2, uint32_t& a3, const void* p) {
    uint32_t s = (uint32_t)__cvta_generic_to_shared(p);
    asm volatile("ldmatrix.sync.aligned.m8n8.x4.shared.b16 {%0,%1,%2,%3}, [%4];\n"
                 : "=r"(a0), "=r"(a1), "=r"(a2), "=r"(a3) : "r"(s));
}
__device__ __forceinline__ void ldsm_x2(uint32_t& b0, uint32_t& b1, const void* p) {
    uint32_t s = (uint32_t)__cvta_generic_to_shared(p);
    asm volatile("ldmatrix.sync.aligned.m8n8.x2.shared.b16 {%0,%1}, [%2];\n"
                 : "=r"(b0), "=r"(b1) : "r"(s));
}
__device__ __forceinline__ void ldsm_x4t(uint32_t& b0, uint32_t& b1, uint32_t& b2, uint32_t& b3, const void* p) {
    uint32_t s = (uint32_t)__cvta_generic_to_shared(p);
    asm volatile("ldmatrix.sync.aligned.m8n8.x4.trans.shared.b16 {%0,%1,%2,%3}, [%4];\n"
                 : "=r"(b0), "=r"(b1), "=r"(b2), "=r"(b3) : "r"(s));
}
__device__ __forceinline__ void mma16816(float* d, uint32_t a0, uint32_t a1, uint32_t a2, uint32_t a3,
                                         uint32_t b0, uint32_t b1) {
    asm volatile("mma.sync.aligned.m16n8k16.row.col.f32.bf16.bf16.f32 "
                 "{%0,%1,%2,%3}, {%4,%5,%6,%7}, {%8,%9}, {%0,%1,%2,%3};\n"
                 : "+f"(d[0]), "+f"(d[1]), "+f"(d[2]), "+f"(d[3])
                 : "r"(a0), "r"(a1), "r"(a2), "r"(a3), "r"(b0), "r"(b1));
}
__device__ __forceinline__ uint32_t pack_bf2(float lo, float hi) {
    __nv_bfloat162 h = __floats2bfloat162_rn(lo, hi);
    return *(uint32_t*)&h;
}

// ---------------- kernel 1: q/k/v projection (tensor core), t-tile 128, 256 thr ----------------
#define QKV_SMEM 135168
__global__ void __launch_bounds__(256, 1)
k_qkv(const float* __restrict__ x,
      const float* __restrict__ wq, const float* __restrict__ bq,
      const float* __restrict__ wk, const float* __restrict__ bk,
      const float* __restrict__ wv, const float* __restrict__ bv)
{
    extern __shared__ char sm8[];
    __nv_bfloat16* Xs = (__nv_bfloat16*)sm8;              // [128 t][264 c]
    __nv_bfloat16* Ws = (__nv_bfloat16*)(sm8 + 67584);    // [128 o][264 c] / stage [128][136]

    const int tid = threadIdx.x, lane = tid & 31, wid = tid >> 5;
    const int t0 = blockIdx.x * 128, n = blockIdx.y;
    const int g = lane >> 2, tg = lane & 3;

    for (int i = tid; i < 256*32; i += 256) {
        int c = i >> 5, t4 = (i & 31) * 4;
        float4 v = *(const float4*)(x + (size_t)(n*CIN + c)*HW + t0 + t4);
        Xs[(t4+0)*264 + c] = __float2bfloat16(v.x);
        Xs[(t4+1)*264 + c] = __float2bfloat16(v.y);
        Xs[(t4+2)*264 + c] = __float2bfloat16(v.z);
        Xs[(t4+3)*264 + c] = __float2bfloat16(v.w);
    }

#pragma unroll 1
    for (int m = 0; m < 3; m++) {
        const float* wp = (m == 0) ? wq : (m == 1) ? wk : wv;
        const float* bp = (m == 0) ? bq : (m == 1) ? bk : bv;
        const float sc = (m == 0) ? QSCALE : 1.0f;
        __syncthreads();
        for (int i = tid; i < 128*64; i += 256) {
            int o = i >> 6, c4 = (i & 63) * 4;
            float4 v = *(const float4*)(wp + o*CIN + c4);
            Ws[o*264 + c4 + 0] = __float2bfloat16(v.x);
            Ws[o*264 + c4 + 1] = __float2bfloat16(v.y);
            Ws[o*264 + c4 + 2] = __float2bfloat16(v.z);
            Ws[o*264 + c4 + 3] = __float2bfloat16(v.w);
        }
        __syncthreads();

        float acc[16][4];
#pragma unroll
        for (int j = 0; j < 16; j++)
#pragma unroll
            for (int q = 0; q < 4; q++) acc[j][q] = 0.f;

#pragma unroll
        for (int kk = 0; kk < 16; kk++) {
            uint32_t a0, a1, a2, a3;
            ldsm_x4(a0, a1, a2, a3, Xs + (wid*16 + (lane & 15))*264 + kk*16 + (lane >> 4)*8);
#pragma unroll
            for (int j = 0; j < 16; j++) {
                uint32_t b0, b1;
                ldsm_x2(b0, b1, Ws + (j*8 + (lane & 7))*264 + kk*16 + ((lane >> 3) & 1)*8);
                mma16816(acc[j], a0, a1, a2, a3, b0, b1);
            }
        }
        __syncthreads();

        __nv_bfloat16* Tb = Ws;   // [128][136]
#pragma unroll
        for (int j = 0; j < 16; j++) {
            int o = j*8 + tg*2;
            float b0 = __ldg(bp + o), b1 = __ldg(bp + o + 1);
            Tb[(wid*16 + g)*136 + o]         = __float2bfloat16((acc[j][0] + b0) * sc);
            Tb[(wid*16 + g)*136 + o + 1]     = __float2bfloat16((acc[j][1] + b1) * sc);
            Tb[(wid*16 + g + 8)*136 + o]     = __float2bfloat16((acc[j][2] + b0) * sc);
            Tb[(wid*16 + g + 8)*136 + o + 1] = __float2bfloat16((acc[j][3] + b1) * sc);
        }
        __syncthreads();
        __nv_bfloat16* gdst = (m == 0) ? g_qT : (m == 1) ? g_kT : g_vT;
        for (int i = tid; i < 128*16; i += 256) {
            int r = i >> 4, ch = i & 15;
            *(uint4*)(gdst + (size_t)(n*HW + t0 + r)*CMID + ch*8) =
                *(const uint4*)(Tb + r*136 + ch*8);
        }
    }
}

// ---------------- kernel 2: attention, 512 threads, pipelined threefry ----------------
// warps: tgrp = wid&7 (16 t-rows each), half = wid>>3 (s-half / c-half)
// mask bits for s-tile it+1 computed interleaved into GEMM2 of s-tile it.
#define ATTN_SMEM 209408
__global__ void __launch_bounds__(512, 1)
k_attn()
{
    extern __shared__ char sm8[];
    __nv_bfloat16* Qs  = (__nv_bfloat16*)sm8;               // [128][136]
    __nv_bfloat16* Kb0 = (__nv_bfloat16*)(sm8 + 34816);
    __nv_bfloat16* Kb1 = (__nv_bfloat16*)(sm8 + 69632);
    __nv_bfloat16* Vb0 = (__nv_bfloat16*)(sm8 + 104448);
    __nv_bfloat16* Vb1 = (__nv_bfloat16*)(sm8 + 139264);
    __nv_bfloat16* Ps  = (__nv_bfloat16*)(sm8 + 174080);    // [128 t][136 s]
    float*         dsh = (float*)(sm8 + 208896);            // [128]

    const int tid = threadIdx.x, lane = tid & 31, wid = tid >> 5;
    const int tgrp = wid & 7, half = wid >> 3;
    const int t0 = blockIdx.x * 128, n = blockIdx.y;
    const int g = lane >> 2, tg = lane & 3;

    if (tid < 128) dsh[tid] = 0.f;

    for (int i = tid; i < 128*16; i += 512) {
        int r = i >> 4, ch = i & 15;
        size_t go = (size_t)(n*HW + r)*CMID + ch*8;
        cp16(Qs  + r*136 + ch*8, g_qT + (size_t)(n*HW + t0 + r)*CMID + ch*8);
        cp16(Kb0 + r*136 + ch*8, g_kT + go);
        cp16(Vb0 + r*136 + ch*8, g_vT + go);
    }
    asm volatile("cp.async.commit_group;\n");

    // threefry counter bases for this thread's 32 elements per s-tile:
    // rows trow, trow+8; cols scol0 + {0,1} + j*8, j = 0..7
    const uint32_t fbase = ((uint32_t)n << 24) + (uint32_t)(t0 + tgrp*16 + g)*4096u
                         + (uint32_t)(half*64 + tg*2);

    // prologue: mask bits for s-tile 0 (bit j*4+q)
    uint32_t bm = 0;
#pragma unroll
    for (int j = 0; j < 8; j++) {
        uint32_t f0 = fbase + (uint32_t)(j*8);
        uint32_t f1 = f0 + 8u*4096u;
        bm |= (thf_bits(f0)    < MASK_THRESH ? 1u : 0u) << (j*4 + 0);
        bm |= (thf_bits(f0+1u) < MASK_THRESH ? 1u : 0u) << (j*4 + 1);
        bm |= (thf_bits(f1)    < MASK_THRESH ? 1u : 0u) << (j*4 + 2);
        bm |= (thf_bits(f1+1u) < MASK_THRESH ? 1u : 0u) << (j*4 + 3);
    }

    float Z[8][4];
#pragma unroll
    for (int jc = 0; jc < 8; jc++)
#pragma unroll
        for (int q = 0; q < 4; q++) Z[jc][q] = 0.f;
    float dsum0 = 0.f, dsum1 = 0.f;

#pragma unroll 1
    for (int it = 0; it < 32; it++) {
        const __nv_bfloat16* K_ = (it & 1) ? Kb1 : Kb0;
        const __nv_bfloat16* V_ = (it & 1) ? Vb1 : Vb0;
        if (it + 1 < 32) {
            __nv_bfloat16* Kn = ((it+1) & 1) ? Kb1 : Kb0;
            __nv_bfloat16* Vn = ((it+1) & 1) ? Vb1 : Vb0;
            int s0n = (it + 1) * 128;
            for (int i = tid; i < 128*16; i += 512) {
                int r = i >> 4, ch = i & 15;
                size_t go = (size_t)(n*HW + s0n + r)*CMID + ch*8;
                cp16(Kn + r*136 + ch*8, g_kT + go);
                cp16(Vn + r*136 + ch*8, g_vT + go);
            }
            asm volatile("cp.async.commit_group;\n");
            asm volatile("cp.async.wait_group 1;\n");
        } else {
            asm volatile("cp.async.wait_group 0;\n");
        }
        __syncthreads();   // K/V ready; all warps done reading Ps of prev iter

        // ---- GEMM1: S[16t x 64s] (this warp's s-half) ----
        float S[8][4];
#pragma unroll
        for (int j = 0; j < 8; j++)
#pragma unroll
            for (int q = 0; q < 4; q++) S[j][q] = 0.f;
#pragma unroll
        for (int kk = 0; kk < 8; kk++) {
            uint32_t a0, a1, a2, a3;
            ldsm_x4(a0, a1, a2, a3, Qs + (tgrp*16 + (lane & 15))*136 + kk*16 + (lane >> 4)*8);
#pragma unroll
            for (int j = 0; j < 8; j += 2) {
                uint32_t b0, b1, b2, b3;
                ldsm_x4(b0, b1, b2, b3,
                        K_ + (half*64 + j*8 + (lane & 7) + ((lane >> 4) & 1)*8)*136
                           + kk*16 + ((lane >> 3) & 1)*8);
                mma16816(S[j],   a0, a1, a2, a3, b0, b1);
                mma16816(S[j+1], a0, a1, a2, a3, b2, b3);
            }
        }

        // ---- apply precomputed mask + ex2, stage P[t][s] bf16 ----
#pragma unroll
        for (int j = 0; j < 8; j++) {
            S[j][0] = ((bm >> (j*4 + 0)) & 1u) ? 0.f : ex2f_(S[j][0]);
            S[j][1] = ((bm >> (j*4 + 1)) & 1u) ? 0.f : ex2f_(S[j][1]);
            S[j][2] = ((bm >> (j*4 + 2)) & 1u) ? 0.f : ex2f_(S[j][2]);
            S[j][3] = ((bm >> (j*4 + 3)) & 1u) ? 0.f : ex2f_(S[j][3]);
            dsum0 += S[j][0] + S[j][1];
            dsum1 += S[j][2] + S[j][3];
            int col = half*64 + tg*2 + j*8;
            *(uint32_t*)(Ps + (tgrp*16 + g)*136 + col)     = pack_bf2(S[j][0], S[j][1]);
            *(uint32_t*)(Ps + (tgrp*16 + g + 8)*136 + col) = pack_bf2(S[j][2], S[j][3]);
        }
        __syncthreads();   // P complete

        // ---- GEMM2 (c-half) interleaved with threefry for s-tile it+1 ----
        const uint32_t fbn = fbase + (uint32_t)((it + 1) * 128);
        const bool mk = (it + 1 < 32);
        uint32_t bmn = 0;
#pragma unroll
        for (int kk = 0; kk < 8; kk++) {
            uint32_t a0, a1, a2, a3;
            ldsm_x4(a0, a1, a2, a3, Ps + (tgrp*16 + (lane & 15))*136 + kk*16 + (lane >> 4)*8);
            // 4 independent threefry calls — fill tensor-pipe shadow
            if (mk) {
                uint32_t f0 = fbn + (uint32_t)(kk*8);
                uint32_t f1 = f0 + 8u*4096u;
                bmn |= (thf_bits(f0)    < MASK_THRESH ? 1u : 0u) << (kk*4 + 0);
                bmn |= (thf_bits(f0+1u) < MASK_THRESH ? 1u : 0u) << (kk*4 + 1);
                bmn |= (thf_bits(f1)    < MASK_THRESH ? 1u : 0u) << (kk*4 + 2);
                bmn |= (thf_bits(f1+1u) < MASK_THRESH ? 1u : 0u) << (kk*4 + 3);
            }
#pragma unroll
            for (int jc = 0; jc < 8; jc += 2) {
                uint32_t b0, b1, b2, b3;
                ldsm_x4t(b0, b1, b2, b3,
                         V_ + (kk*16 + (lane & 7) + ((lane >> 3) & 1)*8)*136
                            + half*64 + jc*8 + ((lane >> 4) & 1)*8);
                mma16816(Z[jc],   a0, a1, a2, a3, b0, b1);
                mma16816(Z[jc+1], a0, a1, a2, a3, b2, b3);
            }
        }
        bm = bmn;
    }

    // ---- row denominators: quad reduce + cross-s-half combine via smem ----
    dsum0 += __shfl_xor_sync(0xffffffffu, dsum0, 1);
    dsum0 += __shfl_xor_sync(0xffffffffu, dsum0, 2);
    dsum1 += __shfl_xor_sync(0xffffffffu, dsum1, 1);
    dsum1 += __shfl_xor_sync(0xffffffffu, dsum1, 2);
    if (tg == 0) {
        atomicAdd(&dsh[tgrp*16 + g], dsum0);
        atomicAdd(&dsh[tgrp*16 + g + 8], dsum1);
    }
    __syncthreads();
    const float inv0 = 1.f / dsh[tgrp*16 + g];
    const float inv1 = 1.f / dsh[tgrp*16 + g + 8];

    // ---- stage zT[t][c] bf16 (Ps reused), coalesced store ----
    __nv_bfloat16* Tb = Ps;   // [128][136]
#pragma unroll
    for (int jc = 0; jc < 8; jc++) {
        int c = half*64 + jc*8 + tg*2;
        *(uint32_t*)(Tb + (tgrp*16 + g)*136 + c)     = pack_bf2(Z[jc][0]*inv0, Z[jc][1]*inv0);
        *(uint32_t*)(Tb + (tgrp*16 + g + 8)*136 + c) = pack_bf2(Z[jc][2]*inv1, Z[jc][3]*inv1);
    }
    __syncthreads();
    for (int i = tid; i < 128*16; i += 512) {
        int r = i >> 4, ch = i & 15;
        *(uint4*)(g_zT + (size_t)(n*HW + t0 + r)*CMID + ch*8) =
            *(const uint4*)(Tb + r*136 + ch*8);
    }
}

// ---------------- kernel 3: output projection + residual (tensor core) ----------------
#define OUT_SMEM 69632
__global__ void __launch_bounds__(256, 1)
k_out(const float* __restrict__ x, const float* __restrict__ wz,
      const float* __restrict__ bz, float* __restrict__ out)
{
    extern __shared__ char sm8[];
    __nv_bfloat16* Wzs = (__nv_bfloat16*)sm8;               // [128 o][136 c]
    __nv_bfloat16* Zts = (__nv_bfloat16*)(sm8 + 34816);     // [128 t][136 c]
    float*         Os  = (float*)sm8;                        // reuse: [128 o][132 t]

    const int tid = threadIdx.x, lane = tid & 31, wid = tid >> 5;
    const int t0 = blockIdx.x * 128, n = blockIdx.y, o0 = blockIdx.z * 128;
    const int g = lane >> 2, tg = lane & 3;

    for (int i = tid; i < 128*32; i += 256) {
        int o = i >> 5, c4 = (i & 31) * 4;
        float4 v = *(const float4*)(wz + (size_t)(o0 + o)*CMID + c4);
        Wzs[o*136 + c4 + 0] = __float2bfloat16(v.x);
        Wzs[o*136 + c4 + 1] = __float2bfloat16(v.y);
        Wzs[o*136 + c4 + 2] = __float2bfloat16(v.z);
        Wzs[o*136 + c4 + 3] = __float2bfloat16(v.w);
    }
    for (int i = tid; i < 128*16; i += 256) {
        int r = i >> 4, ch = i & 15;
        *(uint4*)(Zts + r*136 + ch*8) =
            *(const uint4*)(g_zT + (size_t)(n*HW + t0 + r)*CMID + ch*8);
    }
    __syncthreads();

    float acc[16][4];
#pragma unroll
    for (int j = 0; j < 16; j++)
#pragma unroll
        for (int q = 0; q < 4; q++) acc[j][q] = 0.f;

#pragma unroll
    for (int kk = 0; kk < 8; kk++) {
        uint32_t a0, a1, a2, a3;
        ldsm_x4(a0, a1, a2, a3, Wzs + (wid*16 + (lane & 15))*136 + kk*16 + (lane >> 4)*8);
#pragma unroll
        for (int j = 0; j < 16; j++) {
            uint32_t b0, b1;
            ldsm_x2(b0, b1, Zts + (j*8 + (lane & 7))*136 + kk*16 + ((lane >> 3) & 1)*8);
            mma16816(acc[j], a0, a1, a2, a3, b0, b1);
        }
    }
    __syncthreads();

#pragma unroll
    for (int j = 0; j < 16; j++) {
        int t = j*8 + tg*2;
        Os[(wid*16 + g)*132 + t]         = acc[j][0];
        Os[(wid*16 + g)*132 + t + 1]     = acc[j][1];
        Os[(wid*16 + g + 8)*132 + t]     = acc[j][2];
        Os[(wid*16 + g + 8)*132 + t + 1] = acc[j][3];
    }
    __syncthreads();

    for (int i = tid; i < 128*32; i += 256) {
        int o = i >> 5, t4 = (i & 31) * 4;
        size_t base = (size_t)(n*CIN + o0 + o)*HW + t0 + t4;
        float bb = __ldg(bz + o0 + o);
        float4 xv = *(const float4*)(x + base);
        float4 r;
        r.x = xv.x + bb + Os[o*132 + t4 + 0];
        r.y = xv.y + bb + Os[o*132 + t4 + 1];
        r.z = xv.z + bb + Os[o*132 + t4 + 2];
        r.w = xv.w + bb + Os[o*132 + t4 + 3];
        *(float4*)(out + base) = r;
    }
}

// ---------------- launcher ----------------
extern "C" void kernel_launch(void* const* d_in, const int* in_sizes, int n_in,
                              void* d_out, int out_size)
{
    const float* x  = (const float*)d_in[0];
    const float* wq = (const float*)d_in[1];
    const float* bq = (const float*)d_in[2];
    const float* wk = (const float*)d_in[3];
    const float* bk = (const float*)d_in[4];
    const float* wv = (const float*)d_in[5];
    const float* bv = (const float*)d_in[6];
    const float* wz = (const float*)d_in[7];
    const float* bz = (const float*)d_in[8];
    float* out = (float*)d_out;

    cudaFuncSetAttribute(k_qkv,  cudaFuncAttributeMaxDynamicSharedMemorySize, QKV_SMEM);
    cudaFuncSetAttribute(k_attn, cudaFuncAttributeMaxDynamicSharedMemorySize, ATTN_SMEM);
    cudaFuncSetAttribute(k_out,  cudaFuncAttributeMaxDynamicSharedMemorySize, OUT_SMEM);

    k_qkv <<<dim3(32, 4),    256, QKV_SMEM>>>(x, wq, bq, wk, bk, wv, bv);
    k_attn<<<dim3(32, 4),    512, ATTN_SMEM>>>();
    k_out <<<dim3(32, 4, 2), 256, OUT_SMEM>>>(x, wz, bz, out);
}